// round 4
// baseline (speedup 1.0000x reference)
#include <cuda_runtime.h>
#include <cuda_fp16.h>
#include <cstdint>

// ---------------- problem constants ----------------
#define INDIM 4096
#define NGRP  16
#define NOUT  256

// ---------------- device scratch ----------------
__device__ __half g_Wm[NGRP][128][256];   // folded mid weights [g][n][k]
__device__ float  g_cmid[NGRP][128];      // folded constants
__device__ __half g_Wr[NOUT][2048];       // root weights [n][k]

// ---------------- helpers ----------------
__device__ __forceinline__ unsigned smem_u32(const void* p) {
    unsigned a;
    asm("{ .reg .u64 t; cvta.to.shared.u64 t, %1; cvt.u32.u64 %0, t; }" : "=r"(a) : "l"(p));
    return a;
}
__device__ __forceinline__ void cp_async16(unsigned s, const void* g) {
    asm volatile("cp.async.cg.shared.global [%0], [%1], 16;" :: "r"(s), "l"(g));
}
#define CP_COMMIT() asm volatile("cp.async.commit_group;")
#define CP_WAIT(N)  asm volatile("cp.async.wait_group " #N ";")

__device__ __forceinline__ void ldsm4(unsigned& r0, unsigned& r1, unsigned& r2, unsigned& r3,
                                      unsigned addr) {
    asm volatile("ldmatrix.sync.aligned.m8n8.x4.shared.b16 {%0,%1,%2,%3}, [%4];"
                 : "=r"(r0), "=r"(r1), "=r"(r2), "=r"(r3) : "r"(addr));
}
__device__ __forceinline__ void mma16816(float* c, const unsigned* a, unsigned b0, unsigned b1) {
    asm volatile(
        "mma.sync.aligned.m16n8k16.row.col.f32.f16.f16.f32 "
        "{%0,%1,%2,%3},{%4,%5,%6,%7},{%8,%9},{%0,%1,%2,%3};"
        : "+f"(c[0]), "+f"(c[1]), "+f"(c[2]), "+f"(c[3])
        : "r"(a[0]), "r"(a[1]), "r"(a[2]), "r"(a[3]), "r"(b0), "r"(b1));
}
__device__ __forceinline__ float fast_tanh(float v) {
    v = fminf(fmaxf(v, -15.f), 15.f);
    float e = __expf(2.f * v);
    return __fdividef(e - 1.f, e + 1.f);
}

// ---------------- prep ----------------
__global__ void k_prep_mid(const float* __restrict__ w_inp, const float* __restrict__ pbias,
                           const float* __restrict__ W_mid, const float* __restrict__ b_mid) {
    int w = (blockIdx.x * blockDim.x + threadIdx.x) >> 5;    // 0..2047 = (g,n)
    int lane = threadIdx.x & 31;
    int g = w >> 7, n = w & 127;
    float sum = 0.f;
#pragma unroll
    for (int l = 0; l < 8; l++) {
        int j = l * 32 + lane;
        float wm = W_mid[(g * 256 + j) * 128 + n];
        g_Wm[g][n][j] = __float2half_rn(w_inp[g * 256 + j] * wm);
        sum += pbias[(g * 256 + j) >> 6] * wm;
    }
#pragma unroll
    for (int o = 16; o > 0; o >>= 1) sum += __shfl_xor_sync(0xffffffffu, sum, o);
    if (lane == 0) g_cmid[g][n] = sum + b_mid[g * 128 + n];
}
__global__ void k_prep_root(const float* __restrict__ W_root) {
    int idx = blockIdx.x * 256 + threadIdx.x;
    int k = idx >> 8, n = idx & 255;
    g_Wr[n][k] = __float2half_rn(W_root[idx]);
}

// ================= FUSED: 64 batch rows per CTA, 512 threads =================
// smem layout (bytes):
//   XS[3]  @ 0      : [64][68]  f32 = 17408 each  (x staging, 3-deep)
//   WMS[3] @ 52224  : [128][72] f16 = 18432 each  (Wm chunk, 3-deep)
//   XH     @ 107520 : [64][72]  f16 = 9216        (converted x chunk)
//   PB     @ 116736 : [64][136] f16 = 17408       (mid activations)
//   WRB    @ 134144 : [256][136]f16 = 69632       (root weight slice)
#define XS0o   0u
#define WMS0o  52224u
#define XHo    107520u
#define PBo    116736u
#define WRBo   134144u
#define SMEM_TOTAL 203776
#define XSTR 68
#define HSTR 72
#define PSTR 136

__device__ __forceinline__ void issue_x(unsigned sb, const float* __restrict__ x,
                                        long long b0, int cc, int buf, int tid) {
    unsigned xs = sb + XS0o + (unsigned)buf * 17408u;
    unsigned ws = sb + WMS0o + (unsigned)buf * 18432u;
    int g = cc >> 2, c = cc & 3;
    int kg = g * 256 + c * 64;
#pragma unroll
    for (int j = 0; j < 2; j++) {
        int idx = tid + j * 512;
        int r = idx >> 4, c4 = idx & 15;
        cp_async16(xs + (unsigned)(r * XSTR + c4 * 4) * 4u,
                   x + (b0 + r) * INDIM + kg + c4 * 4);
    }
#pragma unroll
    for (int j = 0; j < 2; j++) {
        int idx = tid + j * 512;
        int n = idx >> 3, c8 = idx & 7;
        cp_async16(ws + (unsigned)(n * HSTR + c8 * 8) * 2u,
                   &g_Wm[g][n][c * 64 + c8 * 8]);
    }
    CP_COMMIT();
}

__global__ void __launch_bounds__(512, 1) k_fused(const float* __restrict__ x,
                                                  float* __restrict__ out,
                                                  const float* __restrict__ b_root) {
    extern __shared__ char smem[];
    unsigned sb = smem_u32(smem);
    const int tid = threadIdx.x, lane = tid & 31, wid = tid >> 5;
    const int wm = wid & 1, wn = wid >> 1;            // 2 M-warps x 8 N-warps
    const long long b0 = (long long)blockIdx.x * 64;

    float racc[2][4][4];                              // root acc: 64x256 / 512 thr = 32 regs
#pragma unroll
    for (int i = 0; i < 2; i++)
#pragma unroll
        for (int j = 0; j < 4; j++)
#pragma unroll
            for (int q = 0; q < 4; q++) racc[i][j][q] = 0.f;

    // prologue: chunks 0,1,2 into buffers 0,1,2
    issue_x(sb, x, b0, 0, 0, tid);
    issue_x(sb, x, b0, 1, 1, tid);
    issue_x(sb, x, b0, 2, 2, tid);

    int bufc = 0;
    for (int g = 0; g < NGRP; g++) {
        // root weight slice for this group (own commit group)
#pragma unroll
        for (int j = 0; j < 8; j++) {
            int idx = tid + j * 512;
            int n = idx >> 4, c16 = idx & 15;
            cp_async16(sb + WRBo + (unsigned)(n * PSTR + c16 * 8) * 2u,
                       &g_Wr[n][g * 128 + c16 * 8]);
        }
        CP_COMMIT();

        float macc[2][2][4];                          // mid acc: 64x128 / 512 thr = 16 regs
#pragma unroll
        for (int i = 0; i < 2; i++)
#pragma unroll
            for (int j = 0; j < 2; j++)
#pragma unroll
                for (int q = 0; q < 4; q++) macc[i][j][q] = 0.f;

#pragma unroll
        for (int c = 0; c < 4; c++) {
            // waits derived from exact commit order (see analysis)
            if (c <= 1) { CP_WAIT(3); }
            else if (c == 2) { if (g < NGRP - 1) { CP_WAIT(3); } else { CP_WAIT(2); } }
            else             { if (g < NGRP - 1) { CP_WAIT(2); } else { CP_WAIT(0); } }
            __syncthreads();

            // convert x f32 -> f16 into XH
            const float* XSf = (const float*)(smem + XS0o + (unsigned)bufc * 17408u);
#pragma unroll
            for (int j = 0; j < 4; j++) {
                int idx = tid + j * 512;
                int r = idx >> 5, c2 = (idx & 31) << 1;
                float2 v = *(const float2*)(XSf + r * XSTR + c2);
                *(__half2*)(smem + XHo + (unsigned)(r * HSTR + c2) * 2u) =
                    __floats2half2_rn(v.x, v.y);
            }
            __syncthreads();

            // mid MMA on this chunk (64x128, K=64)
            unsigned Xh = sb + XHo;
            unsigned WMS = sb + WMS0o + (unsigned)bufc * 18432u;
#pragma unroll
            for (int ks = 0; ks < 4; ks++) {
                int k0 = ks * 16;
                int grp = lane >> 3, r = lane & 7;
                int nb = wn * 16 + ((grp >> 1) << 3) + r;
                int kk = k0 + ((grp & 1) << 3);
                unsigned bfr[2][2];
                {
                    unsigned q0, q1, q2, q3;
                    ldsm4(q0, q1, q2, q3, WMS + (unsigned)(nb * HSTR + kk) * 2u);
                    bfr[0][0] = q0; bfr[0][1] = q1;
                    bfr[1][0] = q2; bfr[1][1] = q3;
                }
                int arow = wm * 32 + (lane & 15);
                int acol = k0 + ((lane >> 4) << 3);
                unsigned afr[2][4];
#pragma unroll
                for (int mt = 0; mt < 2; mt++)
                    ldsm4(afr[mt][0], afr[mt][1], afr[mt][2], afr[mt][3],
                          Xh + (unsigned)((arow + mt * 16) * HSTR + acol) * 2u);
#pragma unroll
                for (int mt = 0; mt < 2; mt++)
#pragma unroll
                    for (int nt = 0; nt < 2; nt++)
                        mma16816(macc[mt][nt], afr[mt], bfr[nt][0], bfr[nt][1]);
            }
            __syncthreads();                          // all warps done with XS/WMS[bufc], XH
            int cc_next = g * 4 + c + 3;
            if (cc_next < NGRP * 4) issue_x(sb, x, b0, cc_next, bufc, tid);
            bufc = (bufc == 2) ? 0 : bufc + 1;
        }

        // tanh -> P (fp16)
#pragma unroll
        for (int mt = 0; mt < 2; mt++)
#pragma unroll
            for (int nt = 0; nt < 2; nt++) {
                int bl = wm * 32 + mt * 16 + (lane >> 2);
                int n = wn * 16 + nt * 8 + ((lane & 3) << 1);
                float2 gc = *(const float2*)&g_cmid[g][n];
                *(__half2*)(smem + PBo + (unsigned)(bl * PSTR + n) * 2u) =
                    __floats2half2_rn(fast_tanh(macc[mt][nt][0] + gc.x),
                                      fast_tanh(macc[mt][nt][1] + gc.y));
                *(__half2*)(smem + PBo + (unsigned)((bl + 8) * PSTR + n) * 2u) =
                    __floats2half2_rn(fast_tanh(macc[mt][nt][2] + gc.x),
                                      fast_tanh(macc[mt][nt][3] + gc.y));
            }
        __syncthreads();                              // P visible (WRB completed via c=3 wait)

        // root partial MMA: racc += P[64,128] @ WR[256,128]^T
        unsigned Pb = sb + PBo, Wr = sb + WRBo;
#pragma unroll
        for (int ks = 0; ks < 8; ks++) {
            int k0 = ks * 16;
            unsigned bfr[4][2];
#pragma unroll
            for (int p = 0; p < 2; p++) {
                int grp = lane >> 3, r = lane & 7;
                int n = wn * 32 + p * 16 + ((grp >> 1) << 3) + r;
                int kk = k0 + ((grp & 1) << 3);
                unsigned q0, q1, q2, q3;
                ldsm4(q0, q1, q2, q3, Wr + (unsigned)(n * PSTR + kk) * 2u);
                bfr[2 * p][0] = q0; bfr[2 * p][1] = q1;
                bfr[2 * p + 1][0] = q2; bfr[2 * p + 1][1] = q3;
            }
            int arow = wm * 32 + (lane & 15);
            int acol = k0 + ((lane >> 4) << 3);
            unsigned afr[2][4];
#pragma unroll
            for (int mt = 0; mt < 2; mt++)
                ldsm4(afr[mt][0], afr[mt][1], afr[mt][2], afr[mt][3],
                      Pb + (unsigned)((arow + mt * 16) * PSTR + acol) * 2u);
#pragma unroll
            for (int mt = 0; mt < 2; mt++)
#pragma unroll
                for (int nt = 0; nt < 4; nt++)
                    mma16816(racc[mt][nt], afr[mt], bfr[nt][0], bfr[nt][1]);
        }
        __syncthreads();                              // WR/P reads done before next group
    }

    // epilogue: smem transpose, add b_root, coalesced float4 stores
    float* trans = (float*)smem;                      // [64][260] f32
#pragma unroll
    for (int mt = 0; mt < 2; mt++)
#pragma unroll
        for (int nt = 0; nt < 4; nt++) {
            int bl = wm * 32 + mt * 16 + (lane >> 2);
            int n = wn * 32 + nt * 8 + ((lane & 3) << 1);
            *(float2*)&trans[bl * 260 + n] = make_float2(racc[mt][nt][0], racc[mt][nt][1]);
            *(float2*)&trans[(bl + 8) * 260 + n] = make_float2(racc[mt][nt][2], racc[mt][nt][3]);
        }
    __syncthreads();
#pragma unroll
    for (int j = 0; j < 8; j++) {
        int f4 = tid + j * 512;
        int b = f4 >> 6, n4 = f4 & 63;
        float4 v = *(float4*)&trans[b * 260 + n4 * 4];
        float4 br = *(const float4*)&b_root[n4 * 4];
        v.x += br.x; v.y += br.y; v.z += br.z; v.w += br.w;
        *(float4*)&out[(b0 + b) * NOUT + n4 * 4] = v;
    }
}

// ---------------- launch ----------------
extern "C" void kernel_launch(void* const* d_in, const int* in_sizes, int n_in,
                              void* d_out, int out_size) {
    const float* x      = (const float*)d_in[0];
    const float* w_inp  = (const float*)d_in[1];
    const float* pbias  = (const float*)d_in[2];
    const float* W_mid  = (const float*)d_in[3];
    const float* b_mid  = (const float*)d_in[4];
    const float* W_root = (const float*)d_in[5];
    const float* b_root = (const float*)d_in[6];
    float* out = (float*)d_out;

    int batch = in_sizes[0] / INDIM;   // 16384
    int tiles = batch / 64;            // 256 CTAs

    cudaFuncSetAttribute(k_fused, cudaFuncAttributeMaxDynamicSharedMemorySize, SMEM_TOTAL);

    k_prep_mid<<<256, 256>>>(w_inp, pbias, W_mid, b_mid);
    k_prep_root<<<2048, 256>>>(W_root);
    k_fused<<<tiles, 512, SMEM_TOTAL>>>(x, out, b_root);
}